// round 17
// baseline (speedup 1.0000x reference)
#include <cuda_runtime.h>
#include <cuda_bf16.h>
#include <cstdint>

#define DD 1024
#define VV 1024
#define BB 64
#define UU 512
#define TS 513           // U+1 steps
#define G3 3072
#define JJ 1024
#define NCTA 128         // 128 CTAs x 8 j-cols each
#define THREADS 512      // 16 warps: 4 compute (one per SMSP) + 12 stagers
#define MTOT (TS * BB)   // 32832 hs rows

// ---- recurrent dynamic smem byte offsets ----
#define RW_HI 0                      // W hi bf16 [24][1032]
#define RW_LO 49536                  // W lo bf16 [24][1032]
#define RHS0 99072                   // h stages (2x): [64][136] hi + lo
#define RSTG 34816                   // one stage bytes (hi+lo)
#define RHLO 17408                   // lo offset within stage
#define RGH 168704                   // gh exchange [64][26] f32
#define RY  175360                   // tokens
#define REC_SMEM (RY + 256)

// out_mma smem (bf16 units): 4 tiles x [128 rows][stride 24], double buffered
#define OS_STRIDE 24
#define OS_TILE (128 * OS_STRIDE)
#define OS_STAGE (4 * OS_TILE)
#define OS_SMEM_BYTES (2 * OS_STAGE * 2)

// ---------------- f32x2 packed-FMA helpers ----------------
__device__ __forceinline__ unsigned long long pack2(float x, float y) {
    unsigned long long r;
    asm("mov.b64 %0, {%1, %2};" : "=l"(r) : "f"(x), "f"(y));
    return r;
}
__device__ __forceinline__ unsigned long long fma2(unsigned long long a,
                                                   unsigned long long b,
                                                   unsigned long long c) {
    unsigned long long d;
    asm("fma.rn.f32x2 %0, %1, %2, %3;" : "=l"(d) : "l"(a), "l"(b), "l"(c));
    return d;
}
__device__ __forceinline__ float2 unpack2(unsigned long long v) {
    float2 f;
    asm("mov.b64 {%0, %1}, %2;" : "=f"(f.x), "=f"(f.y) : "l"(v));
    return f;
}

// ---------------- mma.sync / ldmatrix (baseline PTX, OK at compute_103) ----------------
__device__ __forceinline__ void mma16816(float* c, const uint32_t* a, const uint32_t* b) {
    asm volatile(
        "mma.sync.aligned.m16n8k16.row.col.f32.bf16.bf16.f32 "
        "{%0,%1,%2,%3}, {%4,%5,%6,%7}, {%8,%9}, {%0,%1,%2,%3};"
        : "+f"(c[0]), "+f"(c[1]), "+f"(c[2]), "+f"(c[3])
        : "r"(a[0]), "r"(a[1]), "r"(a[2]), "r"(a[3]), "r"(b[0]), "r"(b[1]));
}
__device__ __forceinline__ void ldsm_x4(uint32_t* r, uint32_t saddr) {
    asm volatile("ldmatrix.sync.aligned.m8n8.x4.shared.b16 {%0,%1,%2,%3}, [%4];"
        : "=r"(r[0]), "=r"(r[1]), "=r"(r[2]), "=r"(r[3]) : "r"(saddr));
}
__device__ __forceinline__ void ldsm_x2(uint32_t* r, uint32_t saddr) {
    asm volatile("ldmatrix.sync.aligned.m8n8.x2.shared.b16 {%0,%1}, [%2];"
        : "=r"(r[0]), "=r"(r[1]) : "r"(saddr));
}
__device__ __forceinline__ uint32_t smem_u32(const void* p) {
    uint32_t a;
    asm("{ .reg .u64 t; cvta.to.shared.u64 t, %1; cvt.u32.u64 %0, t; }" : "=r"(a) : "l"(p));
    return a;
}

// ---------------- static device scratch (alloc-free rule) ----------------
__device__ __align__(16) float g_table[(size_t)VV * G3];
__device__ __align__(16) __nv_bfloat16 g_hs_hi[(size_t)MTOT * DD];
__device__ __align__(16) __nv_bfloat16 g_hs_lo[(size_t)MTOT * DD];
__device__ __align__(16) __nv_bfloat16 g_lw_hi[(size_t)JJ * DD];
__device__ __align__(16) __nv_bfloat16 g_lw_lo[(size_t)JJ * DD];
__device__ __align__(16) float g_hbuf[2][BB * DD];            // fp32 h (gates path)
__device__ __align__(16) __nv_bfloat16 g_hb_hi[2][BB * DD];   // split-bf16 h (MMA path)
__device__ __align__(16) __nv_bfloat16 g_hb_lo[2][BB * DD];
__device__ __align__(16) unsigned g_cnt8[8 * 32];
__device__ unsigned g_bar_cnt;
__device__ unsigned g_bar_phase;

// ---------------- software grid barrier (init only) ----------------
__device__ __forceinline__ void gsync(unsigned target) {
    __syncthreads();
    if (threadIdx.x == 0) {
        __threadfence();
        unsigned a = atomicAdd(&g_bar_cnt, 1u);
        if (a == (unsigned)gridDim.x - 1u) {
            *(volatile unsigned*)&g_bar_cnt = 0u;
            __threadfence();
            atomicExch(&g_bar_phase, target);
        } else {
            while (*(volatile unsigned*)&g_bar_phase != target) { }
            __threadfence();
        }
    }
    __syncthreads();
}

// ---------------- fp32 GEMM (double-buffered, f32x2): vocab table ----------------
__global__ __launch_bounds__(256, 2) void gemm_nt(
    const float* __restrict__ A, const float* __restrict__ Bm,
    const float* __restrict__ bias, float* __restrict__ C, int ldc)
{
    __shared__ float As[2][16][68];
    __shared__ float Bs[2][16][132];
    const int tid = threadIdx.x;
    const int m0 = blockIdx.y * 64;
    const int n0 = blockIdx.x * 128;
    const int tx = tid & 15;
    const int ty = tid >> 4;
    const int ar = tid >> 2, aq = tid & 3;
    const int br0 = (tid) >> 2, bq0 = tid & 3;
    const int br1 = (tid + 256) >> 2, bq1 = tid & 3;

    unsigned long long acc2[4][4];
#pragma unroll
    for (int i = 0; i < 4; i++)
#pragma unroll
        for (int j = 0; j < 4; j++) acc2[i][j] = 0ull;

    {
        float4 av = *(const float4*)(A + (size_t)(m0 + ar) * 1024 + aq * 4);
        As[0][aq * 4 + 0][ar] = av.x; As[0][aq * 4 + 1][ar] = av.y;
        As[0][aq * 4 + 2][ar] = av.z; As[0][aq * 4 + 3][ar] = av.w;
        float4 b0 = *(const float4*)(Bm + (size_t)(n0 + br0) * 1024 + bq0 * 4);
        Bs[0][bq0 * 4 + 0][br0] = b0.x; Bs[0][bq0 * 4 + 1][br0] = b0.y;
        Bs[0][bq0 * 4 + 2][br0] = b0.z; Bs[0][bq0 * 4 + 3][br0] = b0.w;
        float4 b1 = *(const float4*)(Bm + (size_t)(n0 + br1) * 1024 + bq1 * 4);
        Bs[0][bq1 * 4 + 0][br1] = b1.x; Bs[0][bq1 * 4 + 1][br1] = b1.y;
        Bs[0][bq1 * 4 + 2][br1] = b1.z; Bs[0][bq1 * 4 + 3][br1] = b1.w;
    }
    __syncthreads();

#pragma unroll 1
    for (int it = 0; it < 64; it++) {
        const int cur = it & 1;
        float4 avN, b0N, b1N;
        if (it < 63) {
            const int k0 = (it + 1) * 16;
            avN = *(const float4*)(A + (size_t)(m0 + ar) * 1024 + k0 + aq * 4);
            b0N = *(const float4*)(Bm + (size_t)(n0 + br0) * 1024 + k0 + bq0 * 4);
            b1N = *(const float4*)(Bm + (size_t)(n0 + br1) * 1024 + k0 + bq1 * 4);
        }
#pragma unroll
        for (int kk = 0; kk < 16; kk++) {
            unsigned long long rn2[4];
#pragma unroll
            for (int j = 0; j < 4; j++)
                rn2[j] = *(const unsigned long long*)&Bs[cur][kk][tx * 2 + 32 * j];
#pragma unroll
            for (int i = 0; i < 4; i++) {
                float a = As[cur][kk][ty + 16 * i];
                unsigned long long am = pack2(a, a);
#pragma unroll
                for (int j = 0; j < 4; j++)
                    acc2[i][j] = fma2(am, rn2[j], acc2[i][j]);
            }
        }
        if (it < 63) {
            const int nxt = cur ^ 1;
            As[nxt][aq * 4 + 0][ar] = avN.x; As[nxt][aq * 4 + 1][ar] = avN.y;
            As[nxt][aq * 4 + 2][ar] = avN.z; As[nxt][aq * 4 + 3][ar] = avN.w;
            Bs[nxt][bq0 * 4 + 0][br0] = b0N.x; Bs[nxt][bq0 * 4 + 1][br0] = b0N.y;
            Bs[nxt][bq0 * 4 + 2][br0] = b0N.z; Bs[nxt][bq0 * 4 + 3][br0] = b0N.w;
            Bs[nxt][bq1 * 4 + 0][br1] = b1N.x; Bs[nxt][bq1 * 4 + 1][br1] = b1N.y;
            Bs[nxt][bq1 * 4 + 2][br1] = b1N.z; Bs[nxt][bq1 * 4 + 3][br1] = b1N.w;
            __syncthreads();
        }
    }

    float2 b2[4];
#pragma unroll
    for (int j = 0; j < 4; j++)
        b2[j] = *(const float2*)(bias + n0 + tx * 2 + 32 * j);

#pragma unroll
    for (int i = 0; i < 4; i++) {
        int m = m0 + ty + 16 * i;
#pragma unroll
        for (int j = 0; j < 4; j++) {
            float2 v = unpack2(acc2[i][j]);
            float2 o = {v.x + b2[j].x, v.y + b2[j].y};
            *(float2*)(C + (size_t)m * ldc + n0 + tx * 2 + 32 * j) = o;
        }
    }
}

// ---------------- lw -> bf16 (hi, lo) split ----------------
__global__ void convert_lw(const float* __restrict__ w) {
    int i = blockIdx.x * 256 + threadIdx.x;
    if (i < JJ * DD) {
        float v = w[i];
        __nv_bfloat16 h = __float2bfloat16(v);
        g_lw_hi[i] = h;
        g_lw_lo[i] = __float2bfloat16(v - __bfloat162float(h));
    }
}

// ---------------- persistent GRU recurrence v7: warp-specialized HMMA ----------------
// 128 CTAs x 512 thr. CTA owns 24 W rows (8 j x 3 gates), split-bf16 in smem.
// 4 COMPUTE warps (warp=mt, one per SMSP): 9 independent mma chains each
// (3 nt x 3 split terms), FULL K, A-frags loaded once. 12 STAGER warps own
// all global->smem h staging. Gates by all 512 threads from smem exchange.
__global__ __launch_bounds__(THREADS, 1) void recurrent(
    const float* __restrict__ Whh, const float* __restrict__ bhh,
    const int* __restrict__ y, const float* __restrict__ h0)
{
    extern __shared__ __align__(16) char rsm[];
    __nv_bfloat16* w_hi = (__nv_bfloat16*)(rsm + RW_HI);
    __nv_bfloat16* w_lo = (__nv_bfloat16*)(rsm + RW_LO);
    float* gh_s = (float*)(rsm + RGH);
    int* y_si = (int*)(rsm + RY);
    const uint32_t sb = smem_u32(rsm);

    const int tid = threadIdx.x;
    const int lane = tid & 31;
    const int warp = tid >> 5;
    const int cta = blockIdx.x;

    // gate-thread constants
    const int gb = tid >> 3;
    const int jl = tid & 7;
    const int j = cta * 8 + jl;

    // compute-warp constants (warps 0..3; mt = warp)
    const int mt = warp;
    const int lt = lane >> 3, lrr = lane & 7;
    const uint32_t aoff = ((uint32_t)(mt * 16 + (lt & 1) * 8 + lrr) * 136 + (uint32_t)(lt >> 1) * 8) * 2;
    uint32_t boff[3];
#pragma unroll
    for (int nt = 0; nt < 3; nt++)
        boff[nt] = ((uint32_t)(nt * 8 + lrr) * 1032 + (uint32_t)((lane >> 3) & 1) * 8) * 2;

    // stager constants (warps 4..15): slot e in [0, 384)
    const int se = (warp - 4) * 32 + lane;

    unsigned target = *(volatile unsigned*)&g_bar_phase;

    // ---- W slice -> split bf16 smem, once ----
#pragma unroll 4
    for (int p = 0; p < 12; p++) {
        int e = p * THREADS + tid;
        int rho = e >> 8;
        int f4 = e & 255;
        int grow = (rho >> 3) * 1024 + cta * 8 + (rho & 7);
        float4 wv = *(const float4*)(Whh + (size_t)grow * DD + f4 * 4);
        int u = rho * 1032 + f4 * 4;
        __nv_bfloat16 a0 = __float2bfloat16(wv.x), a1 = __float2bfloat16(wv.y);
        __nv_bfloat16 a2 = __float2bfloat16(wv.z), a3 = __float2bfloat16(wv.w);
        w_hi[u + 0] = a0; w_hi[u + 1] = a1; w_hi[u + 2] = a2; w_hi[u + 3] = a3;
        w_lo[u + 0] = __float2bfloat16(wv.x - __bfloat162float(a0));
        w_lo[u + 1] = __float2bfloat16(wv.y - __bfloat162float(a1));
        w_lo[u + 2] = __float2bfloat16(wv.z - __bfloat162float(a2));
        w_lo[u + 3] = __float2bfloat16(wv.w - __bfloat162float(a3));
    }

    // counters + initial state
    if (cta == 0 && tid < 8) g_cnt8[tid * 32] = 0u;
    for (int e = cta * THREADS + tid; e < BB * DD; e += NCTA * THREADS) {
        float v = h0[e & (DD - 1)];
        g_hbuf[0][e] = v;
        __nv_bfloat16 hh = __float2bfloat16(v);
        g_hb_hi[0][e] = hh;
        g_hb_lo[0][e] = __float2bfloat16(v - __bfloat162float(hh));
    }
    gsync(++target);

    const float brr = bhh[j], bzz = bhh[DD + j], bnn = bhh[2 * DD + j];

#pragma unroll 1
    for (int t = 0; t < TS; t++) {
        const int pp = t & 1, pn = pp ^ 1;

        if (tid < BB) y_si[tid] = (t == 0) ? 0 : y[tid * UU + t - 1];

        if (tid == 0 && t > 0) {
            const unsigned lim = 128u * (unsigned)t;
            unsigned s;
            do {
                s = 0;
#pragma unroll
                for (int q = 0; q < 8; q++) s += *(volatile unsigned*)&g_cnt8[q * 32];
            } while (s < lim);
            __threadfence();
        }
        __syncthreads();

        // stage chunk 0 (stager warps only): [b][k] -> [b-chunked 136-stride]
        if (warp >= 4) {
            const uint4* gh_ = (const uint4*)g_hb_hi[pp];
            const uint4* gl_ = (const uint4*)g_hb_lo[pp];
#pragma unroll 1
            for (int idx = se; idx < 1024; idx += 384) {
                int r = idx >> 4, q = idx & 15;
                uint4 vh = __ldcg(gh_ + r * 128 + q);
                uint4 vl = __ldcg(gl_ + r * 128 + q);
                *(uint4*)(rsm + RHS0 + (r * 136 + q * 8) * 2) = vh;
                *(uint4*)(rsm + RHS0 + RHLO + (r * 136 + q * 8) * 2) = vl;
            }
        }
        __syncthreads();

        // gate operand prefetch (all threads; consumed after mainloop)
        const int tok = y_si[gb];
        const float* tp = g_table + (size_t)tok * G3;
        const float ptr_ = __ldcg(tp + j);
        const float ptz = __ldcg(tp + DD + j);
        const float ptn = __ldcg(tp + 2 * DD + j);
        const float phv = __ldcg(g_hbuf[pp] + gb * DD + j);

        // ---- mainloop: 8 chunks of 128 k ----
        float acc[3][3][4];
#pragma unroll
        for (int nt = 0; nt < 3; nt++)
#pragma unroll
            for (int tm = 0; tm < 3; tm++)
#pragma unroll
                for (int u = 0; u < 4; u++) acc[nt][tm][u] = 0.f;

#pragma unroll 1
        for (int c = 0; c < 8; c++) {
            uint4 pvh[3], pvl[3];
            int npf = 0;
            if (warp >= 4 && c < 7) {
                const uint4* gh_ = (const uint4*)g_hb_hi[pp];
                const uint4* gl_ = (const uint4*)g_hb_lo[pp];
#pragma unroll 1
                for (int idx = se; idx < 1024; idx += 384) {
                    int r = idx >> 4, q = idx & 15;
                    pvh[npf] = __ldcg(gh_ + r * 128 + (c + 1) * 16 + q);
                    pvl[npf] = __ldcg(gl_ + r * 128 + (c + 1) * 16 + q);
                    npf++;
                }
            }
            if (warp < 4) {
                const uint32_t abase = sb + RHS0 + (uint32_t)(c & 1) * RSTG;
#pragma unroll
                for (int kt = 0; kt < 8; kt++) {
                    uint32_t ah[4], al[4];
                    ldsm_x4(ah, abase + aoff + kt * 32);
                    ldsm_x4(al, abase + RHLO + aoff + kt * 32);
                    const uint32_t ko = (uint32_t)(c * 128 + kt * 16) * 2;
#pragma unroll
                    for (int nt = 0; nt < 3; nt++) {
                        uint32_t bh[2], bl[2];
                        ldsm_x2(bh, sb + RW_HI + boff[nt] + ko);
                        ldsm_x2(bl, sb + RW_LO + boff[nt] + ko);
                        mma16816(acc[nt][0], ah, bh);
                        mma16816(acc[nt][1], ah, bl);
                        mma16816(acc[nt][2], al, bh);
                    }
                }
            }
            if (c < 7) {
                if (warp >= 4) {
                    char* dst = rsm + RHS0 + ((c + 1) & 1) * RSTG;
                    int ii = 0;
#pragma unroll 1
                    for (int idx = se; idx < 1024; idx += 384) {
                        int r = idx >> 4, q = idx & 15;
                        *(uint4*)(dst + (r * 136 + q * 8) * 2) = pvh[ii];
                        *(uint4*)(dst + RHLO + (r * 136 + q * 8) * 2) = pvl[ii];
                        ii++;
                    }
                }
                __syncthreads();
            }
        }

        // gh exchange (frag layout verified in R15/R16)
        if (warp < 4) {
            const int g = lane >> 2, ct = lane & 3;
#pragma unroll
            for (int nt = 0; nt < 3; nt++) {
                float2 vA = {acc[nt][0][0] + acc[nt][1][0] + acc[nt][2][0],
                             acc[nt][0][1] + acc[nt][1][1] + acc[nt][2][1]};
                float2 vB = {acc[nt][0][2] + acc[nt][1][2] + acc[nt][2][2],
                             acc[nt][0][3] + acc[nt][1][3] + acc[nt][2][3]};
                *(float2*)(gh_s + (mt * 16 + g) * 26 + nt * 8 + ct * 2) = vA;
                *(float2*)(gh_s + (mt * 16 + g + 8) * 26 + nt * 8 + ct * 2) = vB;
            }
        }
        __syncthreads();

        // gates: one (b, j) per thread
        {
            float sr = gh_s[gb * 26 + jl];
            float sz = gh_s[gb * 26 + 8 + jl];
            float sn = gh_s[gb * 26 + 16 + jl];
            float xr = ptr_ + sr + brr;
            float xz = ptz + sz + bzz;
            float gn = sn + bnn;
            float rg = 1.f / (1.f + __expf(-xr));
            float zg = 1.f / (1.f + __expf(-xz));
            float ng = tanhf(ptn + rg * gn);
            float hv = (1.f - zg) * ng + zg * phv;
            g_hbuf[pn][gb * DD + j] = hv;
            __nv_bfloat16 hh = __float2bfloat16(hv);
            __nv_bfloat16 hl = __float2bfloat16(hv - __bfloat162float(hh));
            g_hb_hi[pn][gb * DD + j] = hh;
            g_hb_lo[pn][gb * DD + j] = hl;
            const size_t hi_ = ((size_t)t * BB + gb) * DD + j;
            g_hs_hi[hi_] = hh;
            g_hs_lo[hi_] = hl;
        }
        __syncthreads();
        if (tid == 0) {
            __threadfence();
            atomicAdd(&g_cnt8[(cta & 7) * 32], 1u);
        }
    }
}

// ---------------- mma.sync bf16-split out-GEMM (unchanged from R16) ----------------
__global__ __launch_bounds__(256, 2) void out_mma(
    const float* __restrict__ bias, float* __restrict__ out)
{
    extern __shared__ __align__(16) __nv_bfloat16 osm[];
    const int tid = threadIdx.x;
    const int wid = tid >> 5;
    const int lane = tid & 31;
    const int wm = wid & 3;
    const int wn = wid >> 2;
    const int g = lane >> 2;
    const int ct = lane & 3;
    const int n0 = blockIdx.x * 128;
    const int m0 = blockIdx.y * 128;

    const __nv_bfloat16* srcs[4];
    {
        int r0 = (tid >> 1) & 127;
        int arow = m0 + r0; if (arow >= MTOT) arow = MTOT - 1;
        srcs[0] = g_hs_hi + (size_t)arow * DD;
        srcs[1] = g_hs_lo + (size_t)arow * DD;
        srcs[2] = g_lw_hi + (size_t)(n0 + r0) * DD;
        srcs[3] = g_lw_lo + (size_t)(n0 + r0) * DD;
    }

    float acc[2][8][4];
#pragma unroll
    for (int mt = 0; mt < 2; mt++)
#pragma unroll
        for (int nt = 0; nt < 8; nt++)
#pragma unroll
            for (int u = 0; u < 4; u++) acc[mt][nt][u] = 0.f;

#pragma unroll
    for (int i = 0; i < 4; i++) {
        int e = i * 256 + tid;
        int tile = e >> 8;
        int r = (e >> 1) & 127;
        int q = e & 1;
        uint4 v = *(const uint4*)(srcs[tile] + q * 8);
        *(uint4*)(osm + tile * OS_TILE + r * OS_STRIDE + q * 8) = v;
    }
    __syncthreads();

    const int fm = wm * 32 + g;
    const int fn = wn * 64 + g;

#pragma unroll 1
    for (int kc = 0; kc < 64; kc++) {
        const int cur = kc & 1;
        uint4 pre[4];
        if (kc < 63) {
            const int ko = (kc + 1) * 16;
#pragma unroll
            for (int i = 0; i < 4; i++) {
                int e = i * 256 + tid;
                int tile = e >> 8;
                int q = e & 1;
                pre[i] = *(const uint4*)(srcs[tile] + ko + q * 8);
            }
        }
        const __nv_bfloat16* st = osm + cur * OS_STAGE;
        uint32_t ah[2][4], al[2][4];
#pragma unroll
        for (int mt = 0; mt < 2; mt++) {
            int base = (fm + mt * 16) * OS_STRIDE + ct * 2;
            ah[mt][0] = *(const uint32_t*)(st + base);
            ah[mt][1] = *(const uint32_t*)(st + base + 8 * OS_STRIDE);
            ah[mt][2] = *(const uint32_t*)(st + base + 8);
            ah[mt][3] = *(const uint32_t*)(st + base + 8 * OS_STRIDE + 8);
            const __nv_bfloat16* stl = st + OS_TILE;
            al[mt][0] = *(const uint32_t*)(stl + base);
            al[mt][1] = *(const uint32_t*)(stl + base + 8 * OS_STRIDE);
            al[mt][2] = *(const uint32_t*)(stl + base + 8);
            al[mt][3] = *(const uint32_t*)(stl + base + 8 * OS_STRIDE + 8);
        }
#pragma unroll
        for (int nt = 0; nt < 8; nt++) {
            int base = (fn + nt * 8) * OS_STRIDE + ct * 2;
            uint32_t bh[2], bl[2];
            const __nv_bfloat16* sbh = st + 2 * OS_TILE;
            const __nv_bfloat16* sbl = st + 3 * OS_TILE;
            bh[0] = *(const uint32_t*)(sbh + base);
            bh[1] = *(const uint32_t*)(sbh + base + 8);
            bl[0] = *(const uint32_t*)(sbl + base);
            bl[1] = *(const uint32_t*)(sbl + base + 8);
#pragma unroll
            for (int mt = 0; mt < 2; mt++) {
                mma16816(acc[mt][nt], ah[mt], bh);
                mma16816(acc[mt][nt], ah[mt], bl);
                mma16816(acc[mt][nt], al[mt], bh);
            }
        }
        if (kc < 63) {
            __nv_bfloat16* dn = osm + (cur ^ 1) * OS_STAGE;
#pragma unroll
            for (int i = 0; i < 4; i++) {
                int e = i * 256 + tid;
                int tile = e >> 8;
                int r = (e >> 1) & 127;
                int q = e & 1;
                *(uint4*)(dn + tile * OS_TILE + r * OS_STRIDE + q * 8) = pre[i];
            }
            __syncthreads();
        }
    }

#pragma unroll
    for (int mt = 0; mt < 2; mt++) {
        const int mA = m0 + wm * 32 + mt * 16 + g;
        const int mB = mA + 8;
#pragma unroll
        for (int nt = 0; nt < 8; nt++) {
            const int col = n0 + wn * 64 + nt * 8 + ct * 2;
            float2 bv = *(const float2*)(bias + col);
            if (mA < MTOT) {
                float* o = out + ((size_t)(mA & 63) * TS + (mA >> 6)) * JJ + col;
                o[0] = acc[mt][nt][0] + bv.x;
                o[1] = acc[mt][nt][1] + bv.y;
            }
            if (mB < MTOT) {
                float* o = out + ((size_t)(mB & 63) * TS + (mB >> 6)) * JJ + col;
                o[0] = acc[mt][nt][2] + bv.x;
                o[1] = acc[mt][nt][3] + bv.y;
            }
        }
    }
}

// ---------------- launch ----------------
extern "C" void kernel_launch(void* const* d_in, const int* in_sizes, int n_in,
                              void* d_out, int out_size) {
    const int*   y     = (const int*)d_in[0];
    const float* embed = (const float*)d_in[1];
    const float* wih   = (const float*)d_in[2];
    const float* bih   = (const float*)d_in[3];
    const float* whh   = (const float*)d_in[4];
    const float* bhh   = (const float*)d_in[5];
    const float* lw    = (const float*)d_in[6];
    const float* lb    = (const float*)d_in[7];
    const float* h0    = (const float*)d_in[8];
    float* out = (float*)d_out;

    float* tbl = nullptr;
    cudaGetSymbolAddress((void**)&tbl, g_table);

    static bool attr_done = false;
    if (!attr_done) {
        cudaFuncSetAttribute(recurrent, cudaFuncAttributeMaxDynamicSharedMemorySize, REC_SMEM);
        cudaFuncSetAttribute(out_mma, cudaFuncAttributeMaxDynamicSharedMemorySize, OS_SMEM_BYTES);
        attr_done = true;
    }

    // 1) vocab table: table[v][0:3072] = embed[v]·W_ih^T + b_ih
    gemm_nt<<<dim3(G3 / 128, VV / 64), 256>>>(embed, wih, bih, tbl, G3);
    // 2) linear_w -> bf16 (hi, lo)
    convert_lw<<<(JJ * DD + 255) / 256, 256>>>(lw);
    // 3) persistent recurrence over 513 steps (warp-specialized HMMA)
    recurrent<<<NCTA, THREADS, REC_SMEM>>>(whh, bhh, y, h0);
    // 4) tensor-core (HMMA) out-GEMM with remap epilogue
    out_mma<<<dim3(JJ / 128, (MTOT + 127) / 128), 256, OS_SMEM_BYTES>>>(lb, out);
}